// round 9
// baseline (speedup 1.0000x reference)
#include <cuda_runtime.h>

using ull = unsigned long long;

namespace {
constexpr int CH = 16;
constexpr int H = 192, W = 192;
constexpr unsigned FULL = 0xffffffffu;
constexpr int NT = 192;

// main tile: 28 out rows x 24 out cols; corr rows 0..29 (lane-mapped); noise 34x36
constexpr int NH = 34, NW = 36;
constexpr int SN_FLOATS = CH * NH * NW;      // 19584 -> 78336 B

// top strip: rows 0..3, x-tiles of 96
constexpr int T_NH = 10, T_NW = 108, T_HSR = 96, T_CR = 6;
constexpr int T_SN = CH * T_NH * T_NW;       // 17280
// side strips: one 24-row band, left+right 4-col strips
constexpr int S_NH = 30, S_NW = 16, S_HSR = 4, S_CR = 26;
constexpr int S_SN = CH * S_NH * S_NW;       // 7680 per side
constexpr int S_HS = 9 * S_CR * S_HSR;       // 936 per side

constexpr int SMEM_BYTES = (T_SN + 9 * T_CR * T_HSR) * 4;  // 89856 (largest mode)

constexpr int N_MAIN = 448;                  // 7 y-bands x 8 x-tiles x 8 batch
constexpr int N_TOP  = 16;
constexpr int N_SIDE = 64;
constexpr int NBLOCKS = N_MAIN + N_TOP + N_SIDE;  // 528
}

__device__ __forceinline__ ull pk(float lo, float hi) {
    ull r; asm("mov.b64 %0, {%1,%2};" : "=l"(r) : "f"(lo), "f"(hi)); return r;
}
__device__ __forceinline__ void upk(ull v, float& lo, float& hi) {
    asm("mov.b64 {%0,%1}, %2;" : "=f"(lo), "=f"(hi) : "l"(v));
}
__device__ __forceinline__ void ffma2(ull& acc, ull m, ull s) {
    asm("fma.rn.f32x2 %0, %1, %2, %0;" : "+l"(acc) : "l"(m), "l"(s));
}

// ---- strip helper (round-8 style): corr (16ch, 4 cols, 9 dj) + horizontal 3-sum
__device__ __forceinline__ void corr_hsum(const float* __restrict__ base, int chStride,
                                          const ull* __restrict__ cE0,
                                          const ull* __restrict__ cE1,
                                          float (&h)[9][4])
{
    ull aE0[5], aE1[5], aM[4];
    float a0s[4], a3s[4];
    #pragma unroll
    for (int i = 0; i < 5; i++) { aE0[i] = 0ull; aE1[i] = 0ull; }
    #pragma unroll
    for (int i = 0; i < 4; i++) { aM[i] = 0ull; a0s[i] = 0.0f; a3s[i] = 0.0f; }

    #pragma unroll
    for (int c = 0; c < CH; c++) {
        const float* row = base + c * chStride;
        float4 A = *(const float4*)(row);
        float4 B = *(const float4*)(row + 4);
        float4 C = *(const float4*)(row + 8);
        ull E0 = pk(A.x, A.y), E1 = pk(A.z, A.w);
        ull E2 = pk(B.x, B.y), E3 = pk(B.z, B.w);
        ull E4 = pk(C.x, C.y), E5 = pk(C.z, C.w);
        ull m0 = cE0[c], m1 = cE1[c];
        float c0, c1, c2, c3;
        upk(m0, c0, c1); upk(m1, c2, c3);
        ull mM = pk(c1, c2);
        ffma2(aE0[0], m0, E0); ffma2(aE1[0], m1, E1);
        ffma2(aE0[1], m0, E1); ffma2(aE1[1], m1, E2);
        ffma2(aE0[2], m0, E2); ffma2(aE1[2], m1, E3);
        ffma2(aE0[3], m0, E3); ffma2(aE1[3], m1, E4);
        ffma2(aE0[4], m0, E4); ffma2(aE1[4], m1, E5);
        ffma2(aM[0], mM, E1); ffma2(aM[1], mM, E2);
        ffma2(aM[2], mM, E3); ffma2(aM[3], mM, E4);
        a0s[0] = fmaf(c0, A.y, a0s[0]);  a3s[0] = fmaf(c3, B.x, a3s[0]);
        a0s[1] = fmaf(c0, A.w, a0s[1]);  a3s[1] = fmaf(c3, B.z, a3s[1]);
        a0s[2] = fmaf(c0, B.y, a0s[2]);  a3s[2] = fmaf(c3, C.x, a3s[2]);
        a0s[3] = fmaf(c0, B.w, a0s[3]);  a3s[3] = fmaf(c3, C.z, a3s[3]);
    }

    #pragma unroll
    for (int dj = 0; dj < 9; dj++) {
        float c0, c1, c2, c3;
        if ((dj & 1) == 0) {
            upk(aE0[dj >> 1], c0, c1); upk(aE1[dj >> 1], c2, c3);
        } else {
            c0 = a0s[dj >> 1]; upk(aM[dj >> 1], c1, c2); c3 = a3s[dj >> 1];
        }
        float c4 = __shfl_down_sync(FULL, c0, 1);
        float c5 = __shfl_down_sync(FULL, c1, 1);
        float t12 = c1 + c2, t34 = c3 + c4;
        h[dj][0] = c0 + t12;
        h[dj][1] = t12 + c3;
        h[dj][2] = c2 + t34;
        h[dj][3] = t34 + c5;
    }
}

__global__ __launch_bounds__(NT, 2)
void noisecorr_kernel(const float* __restrict__ noise, float* __restrict__ out)
{
    extern __shared__ float smem[];
    const int t   = threadIdx.x;
    const int bid = blockIdx.x;
    const float inv = 1.0f / 144.0f;

    if (bid < N_MAIN) {
        // ========== MAIN (warp-autonomous): di 4..8 direct + mirror scatter =====
        float* sN = smem;                   // [16][34][36], row 0 = y0-1, col 0 = tx0-5
        const int b   = bid / 56;
        const int rem = bid - b * 56;
        const int ty  = rem >> 3;
        const int tx  = rem & 7;
        const int y0  = (ty < 6) ? ty * 28 : 164;   // band 6 overlaps band 5 (bitwise-identical)
        const int tx0 = tx * 24;
        const float* nb = noise + (size_t)b * CH * H * W;

        for (int idx = t; idx < SN_FLOATS; idx += NT) {
            int c   = idx / (NH * NW);
            int r2  = idx - c * (NH * NW);
            int nr  = r2 / NW;
            int nc  = r2 - nr * NW;
            int gy = y0 - 1 + nr, gx = tx0 - 5 + nc;
            float v = 0.0f;
            if ((unsigned)gy < (unsigned)H && (unsigned)gx < (unsigned)W)
                v = nb[(c * H + gy) * W + gx];
            sN[idx] = v;
        }
        __syncthreads();   // the ONLY block barrier in main mode

        const int w    = t >> 5;            // warp 0..5 -> out cols q0..q0+3
        const int lane = t & 31;            // corr row (0..29 valid)
        const int q0   = w * 4;
        const int rcl  = min(lane, 29);
        const bool lstore = (lane >= 1) && (lane <= 28);
        const int  oy  = y0 + lane - 1;
        const bool xs  = (tx >= 1) && (tx <= 6);

        #pragma unroll 1
        for (int k = 0; k < 5; k++) {       // di = k + 4
            // corr accumulators: 6 cols (q0-1 .. q0+4) x 9 dj
            ull  pE[5][3];                  // even dj: pairs (u0,u1)(u2,u3)(u4,u5)
            ull  pO[4][2];                  // odd dj: pairs (u1,u2)(u3,u4)
            float e0[4], e1[4];             // odd dj edges u0, u5
            #pragma unroll
            for (int i = 0; i < 5; i++) { pE[i][0] = 0; pE[i][1] = 0; pE[i][2] = 0; }
            #pragma unroll
            for (int i = 0; i < 4; i++) { pO[i][0] = 0; pO[i][1] = 0; e0[i] = 0.0f; e1[i] = 0.0f; }

            const float* srow = &sN[(rcl + k) * NW + q0];
            const float* crow = &sN[rcl * NW + q0 + 4];
            #pragma unroll
            for (int c = 0; c < CH; c++) {
                float4 S0 = *(const float4*)(srow);
                float4 S1 = *(const float4*)(srow + 4);
                float4 S2 = *(const float4*)(srow + 8);
                float2 S3 = *(const float2*)(srow + 12);
                float4 C0 = *(const float4*)(crow);       // c[-1],c0,c1,c2
                float2 C1 = *(const float2*)(crow + 4);   // c3,c4
                srow += NH * NW; crow += NH * NW;

                ull E0 = pk(S0.x, S0.y), E1 = pk(S0.z, S0.w);
                ull E2 = pk(S1.x, S1.y), E3 = pk(S1.z, S1.w);
                ull E4 = pk(S2.x, S2.y), E5 = pk(S2.z, S2.w);
                ull E6 = pk(S3.x, S3.y);
                ull M0 = pk(C0.x, C0.y), M1 = pk(C0.z, C0.w), M2 = pk(C1.x, C1.y);
                ull MA = pk(C0.y, C0.z), MB = pk(C0.w, C1.x);

                // even dj = 2e: (u0,u1)+=M0*E[e]; (u2,u3)+=M1*E[e+1]; (u4,u5)+=M2*E[e+2]
                ffma2(pE[0][0], M0, E0); ffma2(pE[0][1], M1, E1); ffma2(pE[0][2], M2, E2);
                ffma2(pE[1][0], M0, E1); ffma2(pE[1][1], M1, E2); ffma2(pE[1][2], M2, E3);
                ffma2(pE[2][0], M0, E2); ffma2(pE[2][1], M1, E3); ffma2(pE[2][2], M2, E4);
                ffma2(pE[3][0], M0, E3); ffma2(pE[3][1], M1, E4); ffma2(pE[3][2], M2, E5);
                ffma2(pE[4][0], M0, E4); ffma2(pE[4][1], M1, E5); ffma2(pE[4][2], M2, E6);
                // odd dj = 2o+1: (u1,u2)+=MA*E[o+1]; (u3,u4)+=MB*E[o+2]; edges scalar
                ffma2(pO[0][0], MA, E1); ffma2(pO[0][1], MB, E2);
                ffma2(pO[1][0], MA, E2); ffma2(pO[1][1], MB, E3);
                ffma2(pO[2][0], MA, E3); ffma2(pO[2][1], MB, E4);
                ffma2(pO[3][0], MA, E4); ffma2(pO[3][1], MB, E5);
                e0[0] = fmaf(C0.x, S0.y, e0[0]);  e1[0] = fmaf(C1.y, S1.z, e1[0]);
                e0[1] = fmaf(C0.x, S0.w, e0[1]);  e1[1] = fmaf(C1.y, S2.x, e1[1]);
                e0[2] = fmaf(C0.x, S1.y, e0[2]);  e1[2] = fmaf(C1.y, S2.z, e1[2]);
                e0[3] = fmaf(C0.x, S1.w, e0[3]);  e1[3] = fmaf(C1.y, S3.x, e1[3]);
            }

            // per dj: horizontal 3-sum in-thread, vertical 3-sum via lane shuffles
            #pragma unroll
            for (int dj = 0; dj < 9; dj++) {
                float u0, u1, u2, u3, u4, u5;
                if ((dj & 1) == 0) {
                    const int e = dj >> 1;
                    upk(pE[e][0], u0, u1); upk(pE[e][1], u2, u3); upk(pE[e][2], u4, u5);
                } else {
                    const int o = dj >> 1;
                    u0 = e0[o]; upk(pO[o][0], u1, u2); upk(pO[o][1], u3, u4); u5 = e1[o];
                }
                float t01 = u1 + u2, t23 = u3 + u4;
                float h0 = (u0 + t01) * inv;
                float h1 = (t01 + u3) * inv;
                float h2 = (u2 + t23) * inv;
                float h3 = (t23 + u5) * inv;

                float hm0 = __shfl_up_sync(FULL, h0, 1), hp0 = __shfl_down_sync(FULL, h0, 1);
                float hm1 = __shfl_up_sync(FULL, h1, 1), hp1 = __shfl_down_sync(FULL, h1, 1);
                float hm2 = __shfl_up_sync(FULL, h2, 1), hp2 = __shfl_down_sync(FULL, h2, 1);
                float hm3 = __shfl_up_sync(FULL, h3, 1), hp3 = __shfl_down_sync(FULL, h3, 1);

                if (lstore) {
                    float4 o4;
                    o4.x = hm0 + h0 + hp0;
                    o4.y = hm1 + h1 + hp1;
                    o4.z = hm2 + h2 + hp2;
                    o4.w = hm3 + h3 + hp3;
                    const int p = (k + 4) * 9 + dj;
                    float* ob = out + (((size_t)b * 81 + p) * H + oy) * W + tx0 + q0;
                    *(float4*)ob = o4;

                    // mirror: out_{80-p}(y+k, x+dj-4) = out_p(y,x), bitwise equal.
                    // restricted to y in [4,191], x in [4,187] (strips own the rest)
                    if (k >= 1) {
                        const int ym = oy + k;
                        if ((unsigned)(ym - 4) < 188u) {
                            const int pm = 80 - p;
                            const int xb = tx0 + q0 + (dj - 4);
                            float* om = out + (((size_t)b * 81 + pm) * H + ym) * W;
                            if (xs) {
                                if ((dj & 1) == 0) {
                                    *(float2*)&om[xb]     = make_float2(o4.x, o4.y);
                                    *(float2*)&om[xb + 2] = make_float2(o4.z, o4.w);
                                } else {
                                    om[xb] = o4.x;
                                    *(float2*)&om[xb + 1] = make_float2(o4.y, o4.z);
                                    om[xb + 3] = o4.w;
                                }
                            } else {
                                if ((unsigned)(xb + 0 - 4) < 184u) om[xb + 0] = o4.x;
                                if ((unsigned)(xb + 1 - 4) < 184u) om[xb + 1] = o4.y;
                                if ((unsigned)(xb + 2 - 4) < 184u) om[xb + 2] = o4.z;
                                if ((unsigned)(xb + 3 - 4) < 184u) om[xb + 3] = o4.w;
                            }
                        }
                    }
                }
            }
        }
    } else if (bid < N_MAIN + N_TOP) {
        // ========== TOP STRIP: planes di 0..3, out rows 0..3, full width ==========
        float* sN  = smem;
        float* sHS = smem + T_SN;
        const int idx0 = bid - N_MAIN;
        const int b    = idx0 >> 1;
        const int tx0  = (idx0 & 1) * 96;
        const float* nb = noise + (size_t)b * CH * H * W;

        for (int idx = t; idx < T_SN; idx += NT) {
            int c   = idx / (T_NH * T_NW);
            int r2  = idx - c * (T_NH * T_NW);
            int nr  = r2 / T_NW;
            int nc  = r2 - nr * T_NW;
            int gy = nr - 5, gx = tx0 - 5 + nc;
            float v = 0.0f;
            if ((unsigned)gy < (unsigned)H && (unsigned)gx < (unsigned)W)
                v = nb[(c * H + gy) * W + gx];
            sN[idx] = v;
        }
        __syncthreads();

        const int r  = t >> 5;          // 0..5 == corr row, exact
        const int g  = t & 31;
        const int q0 = g * 4;
        const int qc = min(q0, 96);
        const int qv = min(q0, 92);
        const bool hstore = (g < 24);
        const bool vstore = (r >= 1) && (r <= 4) && (g <= 23);
        const int  rv = min(max(r, 1), 4);

        ull cE0[CH], cE1[CH];
        #pragma unroll
        for (int c = 0; c < CH; c++) {
            float4 v = *(const float4*)&sN[(c * T_NH + r + 4) * T_NW + qc + 4];
            cE0[c] = pk(v.x * inv, v.y * inv);
            cE1[c] = pk(v.z * inv, v.w * inv);
        }

        #pragma unroll 1
        for (int di = 0; di < 4; di++) {
            float h[9][4];
            corr_hsum(&sN[(r + di) * T_NW + qc], T_NH * T_NW, cE0, cE1, h);

            __syncthreads();
            if (hstore) {
                #pragma unroll
                for (int dj = 0; dj < 9; dj++)
                    *(float4*)&sHS[(dj * T_CR + r) * T_HSR + q0] =
                        make_float4(h[dj][0], h[dj][1], h[dj][2], h[dj][3]);
            }
            __syncthreads();

            const int oy = r - 1;
            #pragma unroll
            for (int dj = 0; dj < 9; dj++) {
                float4 hm = *(const float4*)&sHS[(dj * T_CR + rv - 1) * T_HSR + qv];
                float4 hp = *(const float4*)&sHS[(dj * T_CR + rv + 1) * T_HSR + qv];
                if (vstore) {
                    float4 o;
                    o.x = hm.x + h[dj][0] + hp.x;
                    o.y = hm.y + h[dj][1] + hp.y;
                    o.z = hm.z + h[dj][2] + hp.z;
                    o.w = hm.w + h[dj][3] + hp.w;
                    const int p = di * 9 + dj;
                    float* ob = out + (((size_t)b * 81 + p) * H + oy) * W + tx0 + q0;
                    *(float4*)ob = o;
                }
            }
        }
    } else {
        // ========== SIDE STRIPS: planes di 0..3, cols 0..3 & 188..191 =============
        float* sNL  = smem;
        float* sNR  = smem + S_SN;
        float* sHSL = smem + 2 * S_SN;
        float* sHSR = smem + 2 * S_SN + S_HS;
        const int idx0 = bid - N_MAIN - N_TOP;
        const int b = idx0 >> 3;
        const int k = idx0 & 7;
        const int y0 = (k == 7) ? 168 : 4 + 24 * k;  // overlap rows bitwise-identical
        const float* nb = noise + (size_t)b * CH * H * W;

        for (int idx = t; idx < 2 * S_SN; idx += NT) {
            int side = idx / S_SN;
            int w2   = idx - side * S_SN;
            int c    = w2 / (S_NH * S_NW);
            int r2   = w2 - c * (S_NH * S_NW);
            int nr   = r2 >> 4;
            int nc   = r2 & 15;
            int gy = y0 - 5 + nr;
            int gx = (side ? 183 : -5) + nc;
            float v = 0.0f;
            if ((unsigned)gy < (unsigned)H && (unsigned)gx < (unsigned)W)
                v = nb[(c * H + gy) * W + gx];
            smem[side ? (S_SN + w2) : w2] = v;
        }
        __syncthreads();

        const bool active = (t < 128);
        const int r  = t >> 2;
        const int g  = t & 3;
        const int gg = g & 1;
        const int sd = g >> 1;
        const int q0 = gg * 4;
        const int rc = min(r, 25);
        const bool hstore = active && (gg == 0) && (r < 26);
        const bool vstore = active && (gg == 0) && (r >= 1) && (r <= 24);
        const int  rv = min(max(r, 1), 24);
        float* sNs  = sd ? sNR : sNL;
        float* sHSs = sd ? sHSR : sHSL;
        const int ox = sd ? 188 : 0;

        ull cE0[CH], cE1[CH];
        if (active) {
            #pragma unroll
            for (int c = 0; c < CH; c++) {
                float4 v = *(const float4*)&sNs[(c * S_NH + rc + 4) * S_NW + q0 + 4];
                cE0[c] = pk(v.x * inv, v.y * inv);
                cE1[c] = pk(v.z * inv, v.w * inv);
            }
        }

        #pragma unroll 1
        for (int di = 0; di < 4; di++) {
            float h[9][4];
            if (active)
                corr_hsum(&sNs[(rc + di) * S_NW + q0], S_NH * S_NW, cE0, cE1, h);

            __syncthreads();
            if (hstore) {
                #pragma unroll
                for (int dj = 0; dj < 9; dj++)
                    *(float4*)&sHSs[(dj * S_CR + r) * S_HSR] =
                        make_float4(h[dj][0], h[dj][1], h[dj][2], h[dj][3]);
            }
            __syncthreads();

            if (active) {
                const int oy = y0 + r - 1;
                #pragma unroll
                for (int dj = 0; dj < 9; dj++) {
                    float4 hm = *(const float4*)&sHSs[(dj * S_CR + rv - 1) * S_HSR];
                    float4 hp = *(const float4*)&sHSs[(dj * S_CR + rv + 1) * S_HSR];
                    if (vstore) {
                        float4 o;
                        o.x = hm.x + h[dj][0] + hp.x;
                        o.y = hm.y + h[dj][1] + hp.y;
                        o.z = hm.z + h[dj][2] + hp.z;
                        o.w = hm.w + h[dj][3] + hp.w;
                        const int p = di * 9 + dj;
                        float* ob = out + (((size_t)b * 81 + p) * H + oy) * W + ox;
                        *(float4*)ob = o;
                    }
                }
            }
        }
    }
}

extern "C" void kernel_launch(void* const* d_in, const int* in_sizes, int n_in,
                              void* d_out, int out_size)
{
    const float* noise = (const float*)d_in[0];
    float* out = (float*)d_out;
    (void)in_sizes; (void)n_in; (void)out_size;

    cudaFuncSetAttribute(noisecorr_kernel,
                         cudaFuncAttributeMaxDynamicSharedMemorySize, SMEM_BYTES);

    noisecorr_kernel<<<NBLOCKS, NT, SMEM_BYTES>>>(noise, out);
}

// round 10
// speedup vs baseline: 1.8174x; 1.8174x over previous
#include <cuda_runtime.h>

using ull = unsigned long long;

namespace {
constexpr int CH = 16;
constexpr int H = 192, W = 192;
constexpr unsigned FULL = 0xffffffffu;
constexpr int NT = 256;

// main tile: 28 out rows x 24 out cols; corr 30 rows; noise rows 34, cols 36
constexpr int NH = 34, NW = 36;
constexpr int CRH = 30;
constexpr int HSR = 24;
constexpr int SN_FLOATS  = CH * NH * NW;     // 19584
constexpr int SHS_FLOATS = 9 * CRH * HSR;    // 6480
constexpr int SMEM_BYTES = (SN_FLOATS + SHS_FLOATS) * 4;  // 104256

// top strip: rows 0..3, x-tiles of 96
constexpr int T_NH = 10, T_NW = 108, T_HSR = 96, T_CR = 6;
constexpr int T_SN = CH * T_NH * T_NW;
// side strips: one 24-row band, left+right 4-col strips
constexpr int S_NH = 30, S_NW = 16, S_HSR = 4, S_CR = 26;
constexpr int S_SN = CH * S_NH * S_NW;
constexpr int S_HS = 9 * S_CR * S_HSR;

constexpr int N_MAIN = 448;
constexpr int N_TOP  = 16;
constexpr int N_SIDE = 64;
constexpr int NBLOCKS = N_MAIN + N_TOP + N_SIDE;
}

template<int N> struct Ic { static constexpr int value = N; };

__device__ __forceinline__ ull pk(float lo, float hi) {
    ull r; asm("mov.b64 %0, {%1,%2};" : "=l"(r) : "f"(lo), "f"(hi)); return r;
}
__device__ __forceinline__ void upk(ull v, float& lo, float& hi) {
    asm("mov.b64 {%0,%1}, %2;" : "=f"(lo), "=f"(hi) : "l"(v));
}
__device__ __forceinline__ void ffma2(ull& acc, ull m, ull s) {
    asm("fma.rn.f32x2 %0, %1, %2, %0;" : "+l"(acc) : "l"(m), "l"(s));
}

// strip helper: corr (16ch, 4 cols, 9 dj) + horizontal 3-sum
__device__ __forceinline__ void corr_hsum(const float* __restrict__ base, int chStride,
                                          const ull* __restrict__ cE0,
                                          const ull* __restrict__ cE1,
                                          float (&h)[9][4])
{
    ull aE0[5], aE1[5], aM[4];
    float a0s[4], a3s[4];
    #pragma unroll
    for (int i = 0; i < 5; i++) { aE0[i] = 0ull; aE1[i] = 0ull; }
    #pragma unroll
    for (int i = 0; i < 4; i++) { aM[i] = 0ull; a0s[i] = 0.0f; a3s[i] = 0.0f; }

    #pragma unroll
    for (int c = 0; c < CH; c++) {
        const float* row = base + c * chStride;
        float4 A = *(const float4*)(row);
        float4 B = *(const float4*)(row + 4);
        float4 C = *(const float4*)(row + 8);
        ull E0 = pk(A.x, A.y), E1 = pk(A.z, A.w);
        ull E2 = pk(B.x, B.y), E3 = pk(B.z, B.w);
        ull E4 = pk(C.x, C.y), E5 = pk(C.z, C.w);
        ull m0 = cE0[c], m1 = cE1[c];
        float c0, c1, c2, c3;
        upk(m0, c0, c1); upk(m1, c2, c3);
        ull mM = pk(c1, c2);
        ffma2(aE0[0], m0, E0); ffma2(aE1[0], m1, E1);
        ffma2(aE0[1], m0, E1); ffma2(aE1[1], m1, E2);
        ffma2(aE0[2], m0, E2); ffma2(aE1[2], m1, E3);
        ffma2(aE0[3], m0, E3); ffma2(aE1[3], m1, E4);
        ffma2(aE0[4], m0, E4); ffma2(aE1[4], m1, E5);
        ffma2(aM[0], mM, E1); ffma2(aM[1], mM, E2);
        ffma2(aM[2], mM, E3); ffma2(aM[3], mM, E4);
        a0s[0] = fmaf(c0, A.y, a0s[0]);  a3s[0] = fmaf(c3, B.x, a3s[0]);
        a0s[1] = fmaf(c0, A.w, a0s[1]);  a3s[1] = fmaf(c3, B.z, a3s[1]);
        a0s[2] = fmaf(c0, B.y, a0s[2]);  a3s[2] = fmaf(c3, C.x, a3s[2]);
        a0s[3] = fmaf(c0, B.w, a0s[3]);  a3s[3] = fmaf(c3, C.z, a3s[3]);
    }

    #pragma unroll
    for (int dj = 0; dj < 9; dj++) {
        float c0, c1, c2, c3;
        if ((dj & 1) == 0) {
            upk(aE0[dj >> 1], c0, c1); upk(aE1[dj >> 1], c2, c3);
        } else {
            c0 = a0s[dj >> 1]; upk(aM[dj >> 1], c1, c2); c3 = a3s[dj >> 1];
        }
        float c4 = __shfl_down_sync(FULL, c0, 1);
        float c5 = __shfl_down_sync(FULL, c1, 1);
        float t12 = c1 + c2, t34 = c3 + c4;
        h[dj][0] = c0 + t12;
        h[dj][1] = t12 + c3;
        h[dj][2] = c2 + t34;
        h[dj][3] = t34 + c5;
    }
}

__global__ __launch_bounds__(NT, 2)
void noisecorr_kernel(const float* __restrict__ noise, float* __restrict__ out)
{
    extern __shared__ float smem[];
    const int t   = threadIdx.x;
    const int bid = blockIdx.x;
    const float inv = 1.0f / 144.0f;

    if (bid < N_MAIN) {
        // ================= MAIN: di 4..8 direct + mirror scatter =================
        float* sN  = smem;                  // [16][34][36], row0 = y0-1, col0 = tx0-5
        float* sHS = smem + SN_FLOATS;      // [9][30][24]
        const int b   = bid / 56;
        const int rem = bid - b * 56;
        const int ty  = rem >> 3;
        const int tx  = rem & 7;
        const int y0  = (ty < 6) ? ty * 28 : 164;   // band 6 overlaps band 5 (bitwise-id)
        const int tx0 = tx * 24;
        const float* nb = noise + (size_t)b * CH * H * W;

        // --- vectorized halo load: aligned LDG.128, split STS (smem offset = 4j-3)
        for (int idx = t; idx < CH * NH * 10; idx += NT) {
            int c   = idx / (NH * 10);
            int r2  = idx - c * (NH * 10);
            int nr  = r2 / 10;
            int j   = r2 - nr * 10;
            int gy = y0 - 1 + nr;
            int gx = tx0 - 8 + 4 * j;
            float4 v = make_float4(0.f, 0.f, 0.f, 0.f);
            if ((unsigned)gy < (unsigned)H && (unsigned)gx < (unsigned)W)
                v = *(const float4*)&nb[(c * H + gy) * W + gx];
            float* dst = &sN[(c * NH + nr) * NW];
            if (j == 0) {
                dst[0] = v.w;
            } else if (j == 9) {
                dst[33] = v.x; dst[34] = v.y; dst[35] = v.z;
            } else {
                int L = 4 * j - 3;
                dst[L] = v.x;
                *(float2*)&dst[L + 1] = make_float2(v.y, v.z);
                dst[L + 3] = v.w;
            }
        }
        __syncthreads();

        const int r  = t >> 3;               // 0..31; rows 30,31 clamped
        const int g  = t & 7;
        const int q0 = g * 4;
        const int qc = min(q0, 24);
        const int qv = min(q0, 20);
        const int rc = min(r, 29);
        const bool hstore = (r < 30) && (g < 6);
        const bool vstore = (r >= 1) && (r <= 28) && (g <= 5);
        const int  rv = min(max(r, 1), 28);
        const bool xs = (tx >= 1) && (tx <= 6);
        const bool ys = (ty != 6);

        ull cE0[CH], cE1[CH];
        #pragma unroll
        for (int c = 0; c < CH; c++) {
            float4 v = *(const float4*)&sN[(c * NH + rc) * NW + qc + 4];
            cE0[c] = pk(v.x * inv, v.y * inv);
            cE1[c] = pk(v.z * inv, v.w * inv);
        }

        const int oy = y0 + r - 1;

        auto run_iter = [&](int k, auto ndjc) {
            constexpr int NDJ = decltype(ndjc)::value;   // 5 (k==0) or 9
            constexpr int NE = (NDJ + 1) / 2;
            constexpr int NO = NDJ / 2;
            ull aE0[NE], aE1[NE], aM[NO];
            float a0s[NO], a3s[NO];
            #pragma unroll
            for (int i = 0; i < NE; i++) { aE0[i] = 0ull; aE1[i] = 0ull; }
            #pragma unroll
            for (int i = 0; i < NO; i++) { aM[i] = 0ull; a0s[i] = 0.f; a3s[i] = 0.f; }

            const float* srow = &sN[(rc + k) * NW + qc];
            #pragma unroll
            for (int c = 0; c < CH; c++) {
                float4 A = *(const float4*)(srow);
                float4 B = *(const float4*)(srow + 4);
                float4 Cv;
                ull E[6];
                E[0] = pk(A.x, A.y); E[1] = pk(A.z, A.w);
                E[2] = pk(B.x, B.y); E[3] = pk(B.z, B.w);
                if constexpr (NDJ == 9) {
                    Cv = *(const float4*)(srow + 8);
                    E[4] = pk(Cv.x, Cv.y); E[5] = pk(Cv.z, Cv.w);
                }
                srow += NH * NW;
                ull m0 = cE0[c], m1 = cE1[c];
                float c0, c1, c2, c3;
                upk(m0, c0, c1); upk(m1, c2, c3);
                ull mM = pk(c1, c2);
                #pragma unroll
                for (int e = 0; e < NE; e++) {
                    ffma2(aE0[e], m0, E[e]); ffma2(aE1[e], m1, E[e + 1]);
                }
                #pragma unroll
                for (int o = 0; o < NO; o++) ffma2(aM[o], mM, E[o + 1]);
                a0s[0] = fmaf(c0, A.y, a0s[0]);  a3s[0] = fmaf(c3, B.x, a3s[0]);
                a0s[1] = fmaf(c0, A.w, a0s[1]);  a3s[1] = fmaf(c3, B.z, a3s[1]);
                if constexpr (NDJ == 9) {
                    a0s[2] = fmaf(c0, B.y, a0s[2]);  a3s[2] = fmaf(c3, Cv.x, a3s[2]);
                    a0s[3] = fmaf(c0, B.w, a0s[3]);  a3s[3] = fmaf(c3, Cv.z, a3s[3]);
                }
            }

            float h[NDJ][4];
            #pragma unroll
            for (int dj = 0; dj < NDJ; dj++) {
                float c0, c1, c2, c3;
                if ((dj & 1) == 0) {
                    upk(aE0[dj >> 1], c0, c1); upk(aE1[dj >> 1], c2, c3);
                } else {
                    c0 = a0s[dj >> 1]; upk(aM[dj >> 1], c1, c2); c3 = a3s[dj >> 1];
                }
                float c4 = __shfl_down_sync(FULL, c0, 1);
                float c5 = __shfl_down_sync(FULL, c1, 1);
                float t12 = c1 + c2, t34 = c3 + c4;
                h[dj][0] = c0 + t12;
                h[dj][1] = t12 + c3;
                h[dj][2] = c2 + t34;
                h[dj][3] = t34 + c5;
            }

            __syncthreads();
            if (hstore) {
                #pragma unroll
                for (int dj = 0; dj < NDJ; dj++)
                    *(float4*)&sHS[(dj * CRH + r) * HSR + q0] =
                        make_float4(h[dj][0], h[dj][1], h[dj][2], h[dj][3]);
            }
            __syncthreads();

            #pragma unroll
            for (int dj = 0; dj < NDJ; dj++) {
                float4 hm = *(const float4*)&sHS[(dj * CRH + rv - 1) * HSR + qv];
                float4 hp = *(const float4*)&sHS[(dj * CRH + rv + 1) * HSR + qv];
                if (vstore) {
                    float4 o4;
                    o4.x = hm.x + h[dj][0] + hp.x;
                    o4.y = hm.y + h[dj][1] + hp.y;
                    o4.z = hm.z + h[dj][2] + hp.z;
                    o4.w = hm.w + h[dj][3] + hp.w;
                    const int p = (k + 4) * 9 + dj;
                    float* ob = out + (((size_t)b * 81 + p) * H + oy) * W + tx0 + q0;
                    *(float4*)ob = o4;

                    if constexpr (NDJ == 9) {
                        // k>=1 mirror: out_{80-p}(y+k, x+dj-4); y in [4,191], x in [4,187]
                        const int ym = oy + k;
                        if ((unsigned)(ym - 4) < 188u) {
                            const int pm = 80 - p;
                            const int xb = tx0 + q0 + (dj - 4);
                            float* om = out + (((size_t)b * 81 + pm) * H + ym) * W;
                            if (xs) {
                                if ((dj & 1) == 0) {
                                    *(float2*)&om[xb]     = make_float2(o4.x, o4.y);
                                    *(float2*)&om[xb + 2] = make_float2(o4.z, o4.w);
                                } else {
                                    om[xb] = o4.x;
                                    *(float2*)&om[xb + 1] = make_float2(o4.y, o4.z);
                                    om[xb + 3] = o4.w;
                                }
                            } else {
                                if ((unsigned)(xb + 0 - 4) < 184u) om[xb + 0] = o4.x;
                                if ((unsigned)(xb + 1 - 4) < 184u) om[xb + 1] = o4.y;
                                if ((unsigned)(xb + 2 - 4) < 184u) om[xb + 2] = o4.z;
                                if ((unsigned)(xb + 3 - 4) < 184u) om[xb + 3] = o4.w;
                            }
                        }
                    } else {
                        // k==0 mirror (dj<4): out_{44-dj}(y, x+dj-4); x in [0,187]
                        if (dj < 4) {
                            const int pm = 44 - dj;
                            const int xb = tx0 + q0 + (dj - 4);
                            float* om = out + (((size_t)b * 81 + pm) * H + oy) * W;
                            if (xs) {
                                if ((dj & 1) == 0) {
                                    *(float2*)&om[xb]     = make_float2(o4.x, o4.y);
                                    *(float2*)&om[xb + 2] = make_float2(o4.z, o4.w);
                                } else {
                                    om[xb] = o4.x;
                                    *(float2*)&om[xb + 1] = make_float2(o4.y, o4.z);
                                    om[xb + 3] = o4.w;
                                }
                            } else {
                                if ((unsigned)(xb + 0) < 188u) om[xb + 0] = o4.x;
                                if ((unsigned)(xb + 1) < 188u) om[xb + 1] = o4.y;
                                if ((unsigned)(xb + 2) < 188u) om[xb + 2] = o4.z;
                                if ((unsigned)(xb + 3) < 188u) om[xb + 3] = o4.w;
                            }
                        }
                    }
                }
            }
        };

        run_iter(0, Ic<5>{});
        #pragma unroll 1
        for (int k = 1; k < 5; k++)
            run_iter(k, Ic<9>{});

    } else if (bid < N_MAIN + N_TOP) {
        // ===== TOP STRIP: planes di 0..3 (rows 0..3, full width) + di=4 right corner
        float* sN  = smem;
        float* sHS = smem + T_SN;
        const int idx0 = bid - N_MAIN;
        const int b    = idx0 >> 1;
        const int tx0  = (idx0 & 1) * 96;
        const float* nb = noise + (size_t)b * CH * H * W;

        for (int idx = t; idx < T_SN; idx += NT) {
            int c   = idx / (T_NH * T_NW);
            int r2  = idx - c * (T_NH * T_NW);
            int nr  = r2 / T_NW;
            int nc  = r2 - nr * T_NW;
            int gy = nr - 5, gx = tx0 - 5 + nc;
            float v = 0.0f;
            if ((unsigned)gy < (unsigned)H && (unsigned)gx < (unsigned)W)
                v = nb[(c * H + gy) * W + gx];
            sN[idx] = v;
        }
        __syncthreads();

        const int r  = t >> 5;          // 0..7; rows 6,7 clamped
        const int g  = t & 31;
        const int q0 = g * 4;
        const int qc = min(q0, 96);
        const int qv = min(q0, 92);
        const int rc = min(r, 5);
        const bool hstore = (r < 6) && (g < 24);
        const bool vstore = (r >= 1) && (r <= 4) && (g <= 23);
        const int  rv = min(max(r, 1), 4);
        const bool corner = (tx0 == 96) && (q0 == 92);   // x 188..191

        ull cE0[CH], cE1[CH];
        #pragma unroll
        for (int c = 0; c < CH; c++) {
            float4 v = *(const float4*)&sN[(c * T_NH + rc + 4) * T_NW + qc + 4];
            cE0[c] = pk(v.x * inv, v.y * inv);
            cE1[c] = pk(v.z * inv, v.w * inv);
        }

        #pragma unroll 1
        for (int di = 0; di < 5; di++) {
            float h[9][4];
            corr_hsum(&sN[(rc + di) * T_NW + qc], T_NH * T_NW, cE0, cE1, h);

            __syncthreads();
            if (hstore) {
                #pragma unroll
                for (int dj = 0; dj < 9; dj++)
                    *(float4*)&sHS[(dj * T_CR + r) * T_HSR + q0] =
                        make_float4(h[dj][0], h[dj][1], h[dj][2], h[dj][3]);
            }
            __syncthreads();

            const int oy = r - 1;
            #pragma unroll
            for (int dj = 0; dj < 9; dj++) {
                float4 hm = *(const float4*)&sHS[(dj * T_CR + rv - 1) * T_HSR + qv];
                float4 hp = *(const float4*)&sHS[(dj * T_CR + rv + 1) * T_HSR + qv];
                bool st = vstore && (di < 4 || (corner && dj >= 5));
                if (st) {
                    float4 o;
                    o.x = hm.x + h[dj][0] + hp.x;
                    o.y = hm.y + h[dj][1] + hp.y;
                    o.z = hm.z + h[dj][2] + hp.z;
                    o.w = hm.w + h[dj][3] + hp.w;
                    const int p = di * 9 + dj;
                    float* ob = out + (((size_t)b * 81 + p) * H + oy) * W + tx0 + q0;
                    *(float4*)ob = o;
                }
            }
        }
    } else {
        // ===== SIDE STRIPS: planes di 0..3 (cols 0..3 & 188..191) + di=4 right dj>=5
        float* sNL  = smem;
        float* sNR  = smem + S_SN;
        float* sHSL = smem + 2 * S_SN;
        float* sHSR = smem + 2 * S_SN + S_HS;
        const int idx0 = bid - N_MAIN - N_TOP;
        const int b = idx0 >> 3;
        const int k = idx0 & 7;
        const int y0 = (k == 7) ? 168 : 4 + 24 * k;  // overlap rows bitwise-identical
        const float* nb = noise + (size_t)b * CH * H * W;

        for (int idx = t; idx < 2 * S_SN; idx += NT) {
            int side = idx / S_SN;
            int w2   = idx - side * S_SN;
            int c    = w2 / (S_NH * S_NW);
            int r2   = w2 - c * (S_NH * S_NW);
            int nr   = r2 >> 4;
            int nc   = r2 & 15;
            int gy = y0 - 5 + nr;
            int gx = (side ? 183 : -5) + nc;
            float v = 0.0f;
            if ((unsigned)gy < (unsigned)H && (unsigned)gx < (unsigned)W)
                v = nb[(c * H + gy) * W + gx];
            smem[side ? (S_SN + w2) : w2] = v;
        }
        __syncthreads();

        const bool active = (t < 128);
        const int r  = t >> 2;
        const int g  = t & 3;
        const int gg = g & 1;
        const int sd = g >> 1;
        const int q0 = gg * 4;
        const int rc = min(r, 25);
        const bool hstore = active && (gg == 0) && (r < 26);
        const bool vstore = active && (gg == 0) && (r >= 1) && (r <= 24);
        const int  rv = min(max(r, 1), 24);
        float* sNs  = sd ? sNR : sNL;
        float* sHSs = sd ? sHSR : sHSL;
        const int ox = sd ? 188 : 0;

        ull cE0[CH], cE1[CH];
        if (active) {
            #pragma unroll
            for (int c = 0; c < CH; c++) {
                float4 v = *(const float4*)&sNs[(c * S_NH + rc + 4) * S_NW + q0 + 4];
                cE0[c] = pk(v.x * inv, v.y * inv);
                cE1[c] = pk(v.z * inv, v.w * inv);
            }
        }

        #pragma unroll 1
        for (int di = 0; di < 5; di++) {
            float h[9][4];
            if (active)
                corr_hsum(&sNs[(rc + di) * S_NW + q0], S_NH * S_NW, cE0, cE1, h);

            __syncthreads();
            if (hstore) {
                #pragma unroll
                for (int dj = 0; dj < 9; dj++)
                    *(float4*)&sHSs[(dj * S_CR + r) * S_HSR] =
                        make_float4(h[dj][0], h[dj][1], h[dj][2], h[dj][3]);
            }
            __syncthreads();

            if (active) {
                const int oy = y0 + r - 1;
                #pragma unroll
                for (int dj = 0; dj < 9; dj++) {
                    float4 hm = *(const float4*)&sHSs[(dj * S_CR + rv - 1) * S_HSR];
                    float4 hp = *(const float4*)&sHSs[(dj * S_CR + rv + 1) * S_HSR];
                    bool st = vstore && (di < 4 || (sd == 1 && dj >= 5));
                    if (st) {
                        float4 o;
                        o.x = hm.x + h[dj][0] + hp.x;
                        o.y = hm.y + h[dj][1] + hp.y;
                        o.z = hm.z + h[dj][2] + hp.z;
                        o.w = hm.w + h[dj][3] + hp.w;
                        const int p = di * 9 + dj;
                        float* ob = out + (((size_t)b * 81 + p) * H + oy) * W + ox;
                        *(float4*)ob = o;
                    }
                }
            }
        }
    }
}

extern "C" void kernel_launch(void* const* d_in, const int* in_sizes, int n_in,
                              void* d_out, int out_size)
{
    const float* noise = (const float*)d_in[0];
    float* out = (float*)d_out;
    (void)in_sizes; (void)n_in; (void)out_size;

    cudaFuncSetAttribute(noisecorr_kernel,
                         cudaFuncAttributeMaxDynamicSharedMemorySize, SMEM_BYTES);

    noisecorr_kernel<<<NBLOCKS, NT, SMEM_BYTES>>>(noise, out);
}